// round 2
// baseline (speedup 1.0000x reference)
#include <cuda_runtime.h>
#include <cuda_bf16.h>

// Problem constants: x is [1, 16, 64, 96, 96] fp32
#define Cn   16
#define Dn   64
#define Hn   96
#define Wn   96
#define HWn  (Hn*Wn)
#define VOLn (Dn*Hn*Wn)
#define KSEL 8          // int(0.5 * 16)

// Tiling
#define TH  32          // output tile height
#define TW  32          // output tile width
#define XR  36          // x/s/t region (tile + halo 2)
#define XS  37          // padded stride (odd)
#define GR  34          // gradient/product region (tile + halo 1)
#define QS  35          // padded stride (odd)
#define QWW 32          // w-boxed width
#define QWS 33          // padded stride (odd)

#define SMEM_FLOATS (3*XR*XS + 2*XR*XS + 6*GR*QS + 6*GR*QWS + 32)

__device__ float d_p[Cn];
__device__ int   d_topidx[KSEL];

__global__ void zero_p_kernel() {
    if (threadIdx.x < Cn) d_p[threadIdx.x] = 0.f;
}

extern __shared__ float smem[];

__global__ __launch_bounds__(1024, 1)
void harris_kernel(const float* __restrict__ x) {
    float* xs  = smem;                  // 3 x 36 x 37 : x slice ring
    float* ss  = xs  + 3*XR*XS;         // 36 x 37     : Sd111(x)
    float* ts  = ss  + XR*XS;           // 36 x 37     : Dd(x)
    float* qs  = ts  + XR*XS;           // 6 x 34 x 35 : products
    float* qw  = qs  + 6*GR*QS;         // 6 x 34 x 33 : w-boxed products
    float* red = qw  + 6*GR*QWS;        // 32          : reduction scratch

    const int tx  = threadIdx.x;
    const int ty  = threadIdx.y;
    const int tid = ty * 32 + tx;
    const int w0  = blockIdx.x * TW;
    const int h0  = blockIdx.y * TH;
    const int c   = blockIdx.z;
    const float* __restrict__ xc = x + (size_t)c * VOLn;

    // d-direction running box ring (per output column, registers)
    float Ss[6], Rl[6];
#pragma unroll
    for (int k = 0; k < 6; k++) { Ss[k] = 0.f; Rl[k] = 0.f; }
    float acc = 0.f;

    // ---- plane loader: depth d -> ring slot (d+3)%3, zero outside volume
    auto load_plane = [&](int d) {
        float* dst = xs + ((d + 3) % 3) * XR * XS;
        const bool din = (d >= 0) && (d < Dn);
        const float* src = xc + (size_t)(din ? d : 0) * HWn;
        for (int i = tid; i < XR * XR; i += 1024) {
            int lh = i / XR, lw = i - lh * XR;
            int gh = h0 - 2 + lh, gw = w0 - 2 + lw;
            float v = 0.f;
            if (din && gh >= 0 && gh < Hn && gw >= 0 && gw < Wn)
                v = __ldg(src + gh * Wn + gw);
            dst[lh * XS + lw] = v;
        }
    };

    // prologue: x(-1) = zeros, x(0)
    load_plane(-1);
    load_plane(0);

    for (int f = 0; f <= Dn; f++) {
        // ---- stage 1: load x(f+1) into ring (overwrites slot of f-2)
        load_plane(f + 1);
        __syncthreads();

        // ---- stage 2: s = x(f-1)+x(f)+x(f+1), t = x(f+1)-x(f-1) on 36x36
        {
            const float* pm = xs + ((f + 2) % 3) * XR * XS;  // f-1
            const float* pc = xs + ((f    ) % 3) * XR * XS;  // f
            const float* pp = xs + ((f + 1) % 3) * XR * XS;  // f+1
            for (int i = tid; i < XR * XR; i += 1024) {
                int lh = i / XR, lw = i - lh * XR;
                int o  = lh * XS + lw;
                float a = pm[o], b = pc[o], d3 = pp[o];
                ss[o] = a + b + d3;
                ts[o] = d3 - a;
            }
        }
        __syncthreads();

        // ---- stage 3: gradients + 6 products on 34x34 (halo 1)
        {
            const bool fin = (f < Dn);
            for (int i = tid; i < GR * GR; i += 1024) {
                int gh = i / GR, gw = i - gh * GR;
                int hh = h0 - 1 + gh, ww = w0 - 1 + gw;
                const float* S = ss + gh * XS + gw;
                const float* T = ts + gh * XS + gw;
                float smm = S[0],      smc = S[1],        smp = S[2];
                float scm = S[XS],                        scp = S[XS + 2];
                float spm = S[2 * XS], spc = S[2 * XS+1], spp = S[2 * XS + 2];
                float gx = (smp - smm) + 2.f * (scp - scm) + (spp - spm);
                float gy = (spm + 2.f * spc + spp) - (smm + 2.f * smc + smp);
                float gz = T[0] + T[1] + T[2]
                         + T[XS] + T[XS + 1] + T[XS + 2]
                         + T[2 * XS] + T[2 * XS + 1] + T[2 * XS + 2];
                // products must be ZERO outside the volume (box zero-padding)
                bool valid = fin && hh >= 0 && hh < Hn && ww >= 0 && ww < Wn;
                if (!valid) { gx = 0.f; gy = 0.f; gz = 0.f; }
                int qo = gh * QS + gw;
                qs[0 * GR * QS + qo] = gx * gx;
                qs[1 * GR * QS + qo] = gy * gy;
                qs[2 * GR * QS + qo] = gz * gz;
                qs[3 * GR * QS + qo] = gx * gy;
                qs[4 * GR * QS + qo] = gx * gz;
                qs[5 * GR * QS + qo] = gy * gz;
            }
        }
        __syncthreads();

        // ---- stage 3b: w-direction box (Sw111) -> 34 x 32
        for (int i = tid; i < GR * QWW; i += 1024) {
            int gh = i / QWW, ow = i - gh * QWW;
            int qo = gh * QS + ow;
#pragma unroll
            for (int k = 0; k < 6; k++) {
                const float* Q = qs + k * GR * QS + qo;
                qw[k * GR * QWS + gh * QWS + ow] = Q[0] + Q[1] + Q[2];
            }
        }
        __syncthreads();

        // ---- stage 4: h-box + d-ring + harris (each thread = one output col)
        {
            float Cq[6];
#pragma unroll
            for (int k = 0; k < 6; k++) {
                const float* Qw = qw + k * GR * QWS + ty * QWS + tx;
                float q3 = Qw[0] + Qw[QWS] + Qw[2 * QWS];  // q(f) hw-boxed
                Cq[k] = Ss[k] + q3;          // q(f-2)+q(f-1)+q(f) = 27*B(f-1)
                Ss[k] = Rl[k] + q3;
                Rl[k] = q3;
            }
            if (f >= 1) {  // emit voxel depth e = f-1
                float det = Cq[0] * (Cq[1] * Cq[2] - Cq[5] * Cq[5])
                          - Cq[3] * (Cq[3] * Cq[2] - Cq[5] * Cq[4])
                          + Cq[4] * (Cq[3] * Cq[5] - Cq[1] * Cq[4]);
                float tr = Cq[0] + Cq[1] + Cq[2];
                acc += det * (1.f / 19683.f) - (0.04f / 729.f) * (tr * tr);
            }
        }
    }

    // ---- block reduction -> atomicAdd into d_p[c]
#pragma unroll
    for (int o = 16; o > 0; o >>= 1)
        acc += __shfl_down_sync(0xffffffffu, acc, o);
    if ((tid & 31) == 0) red[tid >> 5] = acc;
    __syncthreads();
    if (tid < 32) {
        float v = red[tid];
#pragma unroll
        for (int o = 16; o > 0; o >>= 1)
            v += __shfl_down_sync(0xffffffffu, v, o);
        if (tid == 0) atomicAdd(&d_p[c], v);
    }
}

// top-8 with strict-> selection: lowest index wins ties (matches lax.top_k)
__global__ void topk_kernel() {
    if (threadIdx.x == 0 && blockIdx.x == 0) {
        float p[Cn];
        bool used[Cn];
        for (int i = 0; i < Cn; i++) { p[i] = d_p[i]; used[i] = false; }
        for (int j = 0; j < KSEL; j++) {
            int best = -1; float bv = 0.f;
            for (int i = 0; i < Cn; i++) {
                if (used[i]) continue;
                if (best < 0 || p[i] > bv) { best = i; bv = p[i]; }
            }
            used[best] = true;
            d_topidx[j] = best;
        }
    }
}

__global__ void gather_kernel(const float* __restrict__ x, float* __restrict__ out) {
    const int per = VOLn / 4;                 // float4 per channel = 147456
    int j = blockIdx.x * blockDim.x + threadIdx.x;
    if (j >= KSEL * per) return;
    int ch  = j / per;
    int off = j - ch * per;
    int src = d_topidx[ch];
    const float4* s = (const float4*)(x + (size_t)src * VOLn);
    float4* o = (float4*)out;
    o[(size_t)ch * per + off] = s[off];
}

extern "C" void kernel_launch(void* const* d_in, const int* in_sizes, int n_in,
                              void* d_out, int out_size) {
    const float* x = (const float*)d_in[0];   // weights d_in[1..3] are fixed Sobels (hardcoded)
    float* out = (float*)d_out;

    size_t smem_bytes = (size_t)SMEM_FLOATS * sizeof(float);  // ~82 KB
    cudaFuncSetAttribute(harris_kernel,
                         cudaFuncAttributeMaxDynamicSharedMemorySize,
                         (int)smem_bytes);

    zero_p_kernel<<<1, 32>>>();
    dim3 grid(Wn / TW, Hn / TH, Cn);          // (3, 3, 16) = 144 blocks
    harris_kernel<<<grid, dim3(32, 32), smem_bytes>>>(x);
    topk_kernel<<<1, 1>>>();
    int n4 = KSEL * (VOLn / 4);
    gather_kernel<<<(n4 + 255) / 256, 256>>>(x, out);
}

// round 3
// speedup vs baseline: 1.8879x; 1.8879x over previous
#include <cuda_runtime.h>
#include <cuda_bf16.h>

// x: [1, 16, 64, 96, 96] fp32
#define Cn   16
#define Dn   64
#define Hn   96
#define Wn   96
#define HWn  (Hn*Wn)
#define VOLn (Dn*HWn)
#define KSEL 8

// harris kernel tiling
#define RW     32            // region width = warp lanes (interior lanes [2,30))
#define TWI    28            // interior tile width
#define NW     12            // warps per block
#define HPT    3             // h rows per thread
#define RH     (NW*HPT)      // 36 region rows (interior [2,34))
#define DCHUNK 16
#define ND     (Dn/DCHUNK)   // 4
#define NSTEP  (DCHUNK+2)    // 18, divisible by 3 for the register ring

__device__ float d_p[Cn];
__device__ int   d_topidx[KSEL];

__global__ void zero_p_kernel() {
    if (threadIdx.x < Cn) d_p[threadIdx.x] = 0.f;
}

__device__ __forceinline__ float shfl_at(float v, int src) {
    return __shfl_sync(0xffffffffu, v, src & 31);
}

__global__ __launch_bounds__(RW*NW, 1)
void harris_kernel(const float* __restrict__ x) {
    // smem: only h-direction warp-edge exchange. idx = region_row + 1.
    __shared__ float su[3][RH+2][RW];   // u1,u2,u3 (pre-h-stencil)
    __shared__ float sq[6][RH+2][RW];   // w-boxed products
    __shared__ float red[NW];

    const int lane = threadIdx.x;
    const int wy   = threadIdx.y;
    const int R0   = wy * HPT;
    const int w0   = blockIdx.x * TWI;            // 0,28,56,84
    const int h0   = blockIdx.y * (RH - 4);       // 0,32,64
    const int c    = blockIdx.z >> 2;
    const int e0   = (blockIdx.z & 3) * DCHUNK;
    const int w    = w0 + lane - 2;

    // zero the pad rows once (only ever read for masked outputs)
    if (wy == 0) {
        #pragma unroll
        for (int k = 0; k < 3; k++) su[k][0][lane] = 0.f;
        #pragma unroll
        for (int k = 0; k < 6; k++) sq[k][0][lane] = 0.f;
    }
    if (wy == NW-1) {
        #pragma unroll
        for (int k = 0; k < 3; k++) su[k][RH+1][lane] = 0.f;
        #pragma unroll
        for (int k = 0; k < 6; k++) sq[k][RH+1][lane] = 0.f;
    }
    __syncthreads();

    bool hwok[HPT];
    int  hoff[HPT];
    bool vmB[HPT];
    #pragma unroll
    for (int r = 0; r < HPT; r++) {
        int Rr = R0 + r;
        int h  = h0 + Rr - 2;
        hwok[r] = (h >= 0 && h < Hn && w >= 0 && w < Wn);
        hoff[r] = h * Wn + w;
        vmB[r]  = (Rr >= 2 && Rr < RH-2) && (lane >= 2 && lane < RW-2) && (w < Wn);
    }

    const float* __restrict__ xch = x + (size_t)c * VOLn;

    auto loadx = [&](int d, int r) -> float {
        if (hwok[r] && d >= 0 && d < Dn)
            return __ldg(xch + (size_t)d * HWn + hoff[r]);
        return 0.f;
    };

    // running d-direction box state per product per row
    float Ss[6][HPT];   // q(f-2)+q(f-1)
    float Rl[6][HPT];   // q(f-1)
    #pragma unroll
    for (int k = 0; k < 6; k++)
        #pragma unroll
        for (int r = 0; r < HPT; r++) { Ss[k][r] = 0.f; Rl[k][r] = 0.f; }

    float acc = 0.f;

    float xa[HPT], xb[HPT], xc[HPT];
    #pragma unroll
    for (int r = 0; r < HPT; r++) { xa[r] = loadx(e0-2, r); xb[r] = loadx(e0-1, r); }

    // one step at depth slice f: builds hw-boxed products q(f), emits e=f-1
    auto step = [&](int f, float (&XA)[HPT], float (&XB)[HPT], float (&XC)[HPT]) {
        #pragma unroll
        for (int r = 0; r < HPT; r++) XC[r] = loadx(f + 1, r);

        float u1[HPT], u2[HPT], u3[HPT];
        #pragma unroll
        for (int r = 0; r < HPT; r++) {
            float s = XA[r] + XB[r] + XC[r];    // Sd111(x)
            float t = XC[r] - XA[r];            // Dd(x)
            float sl = shfl_at(s, lane-1), sr = shfl_at(s, lane+1);
            float tl = shfl_at(t, lane-1), tr = shfl_at(t, lane+1);
            u1[r] = sr - sl;                    // Dw(s)
            u2[r] = sl + 2.f*s + sr;            // Sw121(s)
            u3[r] = tl + t + tr;                // Sw111(t)
        }
        // exchange edge rows (thread's rows 0 and 2)
        su[0][R0+1][lane] = u1[0]; su[1][R0+1][lane] = u2[0]; su[2][R0+1][lane] = u3[0];
        su[0][R0+3][lane] = u1[2]; su[1][R0+3][lane] = u2[2]; su[2][R0+3][lane] = u3[2];
        __syncthreads();

        const bool fok = (f >= 0 && f < Dn);
        float qw[6][HPT];
        #pragma unroll
        for (int r = 0; r < HPT; r++) {
            float a1 = (r == 0) ? su[0][R0][lane]   : u1[r-1];
            float b1 = (r == 2) ? su[0][R0+4][lane] : u1[r+1];
            float a2 = (r == 0) ? su[1][R0][lane]   : u2[r-1];
            float b2 = (r == 2) ? su[1][R0+4][lane] : u2[r+1];
            float a3 = (r == 0) ? su[2][R0][lane]   : u3[r-1];
            float b3 = (r == 2) ? su[2][R0+4][lane] : u3[r+1];
            float gx = a1 + 2.f*u1[r] + b1;     // Sh121(Dw(s))
            float gy = b2 - a2;                 // Dh(Sw121(s))
            float gz = a3 + u3[r] + b3;         // Sh111(Sw111(t))
            bool pm = fok && hwok[r];           // products ZERO outside volume
            gx = pm ? gx : 0.f;
            gy = pm ? gy : 0.f;
            gz = pm ? gz : 0.f;
            float pp[6] = { gx*gx, gy*gy, gz*gz, gx*gy, gx*gz, gy*gz };
            #pragma unroll
            for (int k = 0; k < 6; k++) {
                float pl = shfl_at(pp[k], lane-1), pr = shfl_at(pp[k], lane+1);
                qw[k][r] = pl + pp[k] + pr;     // Sw111 of products
            }
        }
        #pragma unroll
        for (int k = 0; k < 6; k++) {
            sq[k][R0+1][lane] = qw[k][0];
            sq[k][R0+3][lane] = qw[k][2];
        }
        __syncthreads();

        const bool emit = (f > e0);
        #pragma unroll
        for (int r = 0; r < HPT; r++) {
            float Cv[6];
            #pragma unroll
            for (int k = 0; k < 6; k++) {
                float qm = (r == 0) ? sq[k][R0][lane]   : qw[k][r-1];
                float qp = (r == 2) ? sq[k][R0+4][lane] : qw[k][r+1];
                float qc = qm + qw[k][r] + qp;  // Sh111 -> q(f)
                Cv[k]    = Ss[k][r] + qc;       // q(f-2)+q(f-1)+q(f) = 27*B(f-1)
                Ss[k][r] = Rl[k][r] + qc;
                Rl[k][r] = qc;
            }
            float det = Cv[0]*(Cv[1]*Cv[2] - Cv[5]*Cv[5])
                      - Cv[3]*(Cv[3]*Cv[2] - Cv[5]*Cv[4])
                      + Cv[4]*(Cv[3]*Cv[5] - Cv[1]*Cv[4]);
            float tr  = Cv[0] + Cv[1] + Cv[2];
            float hv  = det * (1.f/19683.f) - (0.04f/729.f) * (tr*tr);
            if (emit && vmB[r]) acc += hv;
        }
    };

    int fb = e0 - 1;
    #pragma unroll 1
    for (int it = 0; it < NSTEP; it += 3) {
        step(fb,   xa, xb, xc);
        step(fb+1, xb, xc, xa);
        step(fb+2, xc, xa, xb);
        fb += 3;
    }

    // block reduce -> atomicAdd
    #pragma unroll
    for (int o = 16; o > 0; o >>= 1)
        acc += __shfl_down_sync(0xffffffffu, acc, o);
    if (lane == 0) red[wy] = acc;
    __syncthreads();
    if (wy == 0) {
        float v = (lane < NW) ? red[lane] : 0.f;
        #pragma unroll
        for (int o = 8; o > 0; o >>= 1)
            v += __shfl_down_sync(0xffffffffu, v, o);
        if (lane == 0) atomicAdd(&d_p[c], v);
    }
}

// top-8, strict > selection: lowest index wins ties (matches lax.top_k)
__global__ void topk_kernel() {
    if (threadIdx.x == 0 && blockIdx.x == 0) {
        float p[Cn];
        bool used[Cn];
        for (int i = 0; i < Cn; i++) { p[i] = d_p[i]; used[i] = false; }
        for (int j = 0; j < KSEL; j++) {
            int best = -1; float bv = 0.f;
            for (int i = 0; i < Cn; i++) {
                if (used[i]) continue;
                if (best < 0 || p[i] > bv) { best = i; bv = p[i]; }
            }
            used[best] = true;
            d_topidx[j] = best;
        }
    }
}

__global__ void gather_kernel(const float* __restrict__ x, float* __restrict__ out) {
    const int per = VOLn / 4;                 // float4 per channel
    int j = blockIdx.x * blockDim.x + threadIdx.x;
    if (j >= KSEL * per) return;
    int ch  = j / per;
    int off = j - ch * per;
    int src = d_topidx[ch];
    const float4* s = (const float4*)(x + (size_t)src * VOLn);
    float4* o = (float4*)out;
    o[(size_t)ch * per + off] = s[off];
}

extern "C" void kernel_launch(void* const* d_in, const int* in_sizes, int n_in,
                              void* d_out, int out_size) {
    const float* x = (const float*)d_in[0];   // Sobel weights are fixed; hardcoded
    float* out = (float*)d_out;

    zero_p_kernel<<<1, 32>>>();
    dim3 grid(4, 3, Cn * ND);                 // (4, 3, 64) = 768 blocks
    harris_kernel<<<grid, dim3(RW, NW)>>>(x);
    topk_kernel<<<1, 1>>>();
    int n4 = KSEL * (VOLn / 4);
    gather_kernel<<<(n4 + 255) / 256, 256>>>(x, out);
}